// round 16
// baseline (speedup 1.0000x reference)
#include <cuda_runtime.h>
#include <cuda_fp16.h>
#include <cooperative_groups.h>

namespace cg = cooperative_groups;

#define CS   8
#define TPB  512

// ---- shared memory layout (float/u32-word offsets) ----
static constexpr int OFF_WHS  = 0;       // 2 * 32*65 words : Whs[bb][q][h2] (half2 per word)
static constexpr int OFF_WGT  = 4160;    // 256*17 words    : WgT[k][j2]
static constexpr int OFF_WIHK = 8512;    // 32*258 words    : WihT_k[k][j2]
static constexpr int OFF_WHHK = 16768;   // 16*258 words    : WhhT_k[k][j2]
static constexpr int OFF_WRK  = 20896;   // 16*66 words     : WrT_k[k][j] (half idx k*132+j)
static constexpr int OFF_WE   = 21952;   // 128 fp32
static constexpr int OFF_WRB  = 22080;   // 128 fp32
static constexpr int OFF_WGB  = 22208;   // 32 fp32
static constexpr int OFF_BIHH = 22240;   // 64 fp32
static constexpr int OFF_MBAR = 22304;   // 16 floats = 8 u64 slots (6 used)
static constexpr int OFF_ST   = 22320;   // per-batch state below
// per-batch state, stride SBS (all fp32)
static constexpr int P_U    = 0;      // 128
static constexpr int P_X    = 128;    // 256 : [alpha, p_t]
static constexpr int P_PQ   = 384;    // 32
static constexpr int P_XM   = 416;    // 32
static constexpr int P_HM   = 448;    // 16
static constexpr int P_C    = 464;    // 16
static constexpr int P_ACB  = 480;    // 8*128 (pushed)
static constexpr int P_LB   = 1504;   // 8     (pushed)
static constexpr int P_UACB = 1512;   // 8*128 (pushed)
static constexpr int P_GIH  = 2536;   // 8*64  (pushed)
static constexpr int P_GHH  = 3048;   // 2*8*64 parity buffered (pushed)
static constexpr int SBS    = 4072;
static constexpr int OFF_STG = OFF_ST + 2 * SBS;     // 30464 : prologue staging (25088)
static constexpr int SMEM_FLOATS = OFF_STG + 25088;  // 55552 floats = 222208 B

__device__ __forceinline__ uint32_t MBB(int bb, int i) {   // i: 0 hp(u), 1 acc, 2 gih+ghh
    return (uint32_t)(OFF_MBAR * 4 + (bb * 3 + i) * 8);
}

__device__ float g_wtp[16 * 128 * 128];   // wt_pre scratch [B][P][H]

__device__ __forceinline__ float fast_tanh(float x) {
    float y; asm("tanh.approx.f32 %0, %1;" : "=f"(y) : "f"(x)); return y;
}
__device__ __forceinline__ float sigm(float x) {
    return __fdividef(1.f, 1.f + __expf(-x));
}
__device__ __forceinline__ float tanh_ex(float x) {
    float e = __expf(2.f * x);
    return 1.f - __fdividef(2.f, e + 1.f);
}
__device__ __forceinline__ float warp_sum(float v) {
    #pragma unroll
    for (int o = 16; o; o >>= 1) v += __shfl_xor_sync(0xffffffffu, v, o);
    return v;
}
__device__ __forceinline__ uint32_t mapa_rank(uint32_t base, int r) {
    uint32_t rm;
    asm("mapa.shared::cluster.u32 %0, %1, %2;" : "=r"(rm) : "r"(base), "r"(r));
    return rm;
}
__device__ __forceinline__ void st_async32(uint32_t rbase, int foff, uint32_t mb_byte, float v) {
    asm volatile("st.async.shared::cluster.mbarrier::complete_tx::bytes.b32 [%0], %1, [%2];"
                 :: "r"(rbase + (uint32_t)foff * 4u), "r"(__float_as_uint(v)),
                    "r"(rbase + mb_byte) : "memory");
}
__device__ __forceinline__ void st_async128(uint32_t rbase, int foff, uint32_t mb_byte,
                                            float a, float b, float c, float d) {
    asm volatile("st.async.shared::cluster.mbarrier::complete_tx::bytes.v4.b32 [%0], {%1,%2,%3,%4}, [%5];"
                 :: "r"(rbase + (uint32_t)foff * 4u),
                    "r"(__float_as_uint(a)), "r"(__float_as_uint(b)),
                    "r"(__float_as_uint(c)), "r"(__float_as_uint(d)),
                    "r"(rbase + mb_byte) : "memory");
}
__device__ __forceinline__ void mbar_init(uint32_t addr) {
    asm volatile("mbarrier.init.shared.b64 [%0], 1;" :: "r"(addr) : "memory");
}
__device__ __forceinline__ void mbar_expect(uint32_t addr, uint32_t bytes) {
    asm volatile("mbarrier.arrive.expect_tx.shared.b64 _, [%0], %1;" :: "r"(addr), "r"(bytes) : "memory");
}
__device__ __forceinline__ void mbar_wait(uint32_t addr, uint32_t parity) {
    asm volatile(
        "{\n\t.reg .pred P1;\n\t"
        "WL%=:\n\t"
        "mbarrier.try_wait.parity.acquire.cluster.shared::cta.b64 P1, [%0], %1, 0x989680;\n\t"
        "@P1 bra.uni WD%=;\n\t"
        "bra.uni WL%=;\n\t"
        "WD%=:\n\t}"
        :: "r"(addr), "r"(parity) : "memory");
}
__device__ __forceinline__ void barg(int bb) {
    asm volatile("bar.sync %0, 256;" :: "r"(1 + bb) : "memory");
}
__device__ __forceinline__ void csync() {
    asm volatile("barrier.cluster.arrive.aligned;" ::: "memory");
    asm volatile("barrier.cluster.wait.aligned;" ::: "memory");
}

__global__ void __launch_bounds__(TPB, 1) __cluster_dims__(CS, 1, 1)
mlstm_kernel(const float* __restrict__ p_in,  const float* __restrict__ q_in,
             const float* __restrict__ Ws_w,  const float* __restrict__ Ws_b,
             const float* __restrict__ Wt_w,  const float* __restrict__ Wt_b,
             const float* __restrict__ Wr_w,  const float* __restrict__ Wr_b,
             const float* __restrict__ We_w,
             const float* __restrict__ Wg_w,  const float* __restrict__ Wg_b,
             const float* __restrict__ Wih,   const float* __restrict__ Whh,
             const float* __restrict__ bih,   const float* __restrict__ bhh,
             float* __restrict__ out)
{
    extern __shared__ float s[];
    __half* sh = (__half*)s;
    cg::cluster_group cl = cg::this_cluster();
    const int rank = (int)cl.block_rank();
    const int b0   = (int)(blockIdx.x >> 3) * 2;
    const int tid  = (int)threadIdx.x;
    const int lane = tid & 31;

    // ============================ PROLOGUE ============================
    // P1: Whs[bb] = q(32 rows) @ Ws^T + b  (Ws staged pad132 at OFF_STG, q at OFF_STG+16896)
    for (int i4 = tid; i4 < 4096; i4 += TPB) {
        int hh = i4 >> 5, k = i4 & 31;
        *(float4*)&s[OFF_STG + hh * 132 + k * 4] = ((const float4*)Ws_w)[i4];
    }
    #pragma unroll
    for (int bb = 0; bb < 2; bb++)
        for (int i4 = tid; i4 < 1024; i4 += TPB)
            ((float4*)&s[OFF_STG + 16896 + bb * 4096])[i4] =
                ((const float4*)(q_in + (size_t)((b0 + bb) * 256 + rank * 32) * 128))[i4];
    __syncthreads();
    #pragma unroll
    for (int bb = 0; bb < 2; bb++) {
        int hh = tid & 127, q0 = (tid >> 7) * 8;
        const float4* wrow = (const float4*)&s[OFF_STG + hh * 132];
        float acc[8];
        float sb = Ws_b[hh];
        #pragma unroll
        for (int i = 0; i < 8; i++) acc[i] = sb;
        for (int k = 0; k < 32; k++) {
            float4 w = wrow[k];
            #pragma unroll
            for (int i = 0; i < 8; i++) {
                float4 qv = *(const float4*)&s[OFF_STG + 16896 + bb * 4096 + (q0 + i) * 128 + k * 4];
                acc[i] += w.x * qv.x + w.y * qv.y + w.z * qv.z + w.w * qv.w;
            }
        }
        #pragma unroll
        for (int i = 0; i < 8; i++)
            sh[(OFF_WHS + bb * 2080) * 2 + (q0 + i) * 130 + hh] = __float2half(acc[i]);
    }
    __syncthreads();

    // P2: wt_pre[bb] = p(16 rows) @ Wt^T + b -> gmem scratch
    for (int i4 = tid; i4 < 4096; i4 += TPB) {
        int hh = i4 >> 5, k = i4 & 31;
        *(float4*)&s[OFF_STG + hh * 132 + k * 4] = ((const float4*)Wt_w)[i4];
    }
    #pragma unroll
    for (int bb = 0; bb < 2; bb++)
        for (int i4 = tid; i4 < 512; i4 += TPB)
            ((float4*)&s[OFF_STG + 16896 + bb * 2048])[i4] =
                ((const float4*)(p_in + (size_t)((b0 + bb) * 128 + rank * 16) * 128))[i4];
    __syncthreads();
    #pragma unroll
    for (int bb = 0; bb < 2; bb++) {
        int hh = tid & 127, t0 = (tid >> 7) * 4;
        const float4* wrow = (const float4*)&s[OFF_STG + hh * 132];
        float acc[4];
        float bt = Wt_b[hh];
        #pragma unroll
        for (int i = 0; i < 4; i++) acc[i] = bt;
        for (int k = 0; k < 32; k++) {
            float4 w = wrow[k];
            #pragma unroll
            for (int i = 0; i < 4; i++) {
                float4 pv = *(const float4*)&s[OFF_STG + 16896 + bb * 2048 + (t0 + i) * 128 + k * 4];
                acc[i] += w.x * pv.x + w.y * pv.y + w.z * pv.z + w.w * pv.w;
            }
        }
        #pragma unroll
        for (int i = 0; i < 4; i++)
            g_wtp[(size_t)((b0 + bb) * 128 + rank * 16 + t0 + i) * 128 + hh] = acc[i];
    }
    __syncthreads();

    // P3: resident weights (k-partitioned, fp16)
    for (int idx = tid; idx < 512 * 32; idx += TPB) {       // WihT_k [k][516 halves]
        int j = idx >> 5, kk = idx & 31;
        sh[OFF_WIHK * 2 + kk * 516 + j] = __float2half(Wih[(size_t)j * 256 + rank * 32 + kk]);
    }
    for (int idx = tid; idx < 512 * 16; idx += TPB) {       // WhhT_k [k][516 halves]
        int j = idx >> 4, kk = idx & 15;
        sh[OFF_WHHK * 2 + kk * 516 + j] = __float2half(Whh[(size_t)j * 128 + rank * 16 + kk]);
    }
    for (int idx = tid; idx < 128 * 16; idx += TPB) {       // WrT_k [k][132 halves]
        int j = idx >> 4, kk = idx & 15;
        sh[OFF_WRK * 2 + kk * 132 + j] = __float2half(Wr_w[(size_t)j * 128 + rank * 16 + kk]);
    }
    for (int idx = tid; idx < 8192; idx += TPB) {           // WgT [k][34 halves]
        int j = idx >> 8, k = idx & 255;
        sh[OFF_WGT * 2 + k * 34 + j] = __float2half(Wg_w[(size_t)(rank * 32 + j) * 256 + k]);
    }
    if (tid < 128) { s[OFF_WE + tid] = We_w[tid]; s[OFF_WRB + tid] = Wr_b[tid]; }
    if (tid < 32) s[OFF_WGB + tid] = Wg_b[rank * 32 + tid];
    if (tid < 64) {
        int grow = (tid >> 4) * 128 + rank * 16 + (tid & 15);
        s[OFF_BIHH + tid] = bih[grow] + bhh[grow];
    }
    #pragma unroll
    for (int bbz = 0; bbz < 2; bbz++) {
        int S = OFF_ST + bbz * SBS;
        for (int i = tid; i < 1024; i += TPB) { s[S + P_UACB + i] = 0.f; s[S + P_GHH + i] = 0.f; }
        if (tid < 16) s[S + P_C + tid] = 0.f;
    }
    const uint32_t sbase = (uint32_t)__cvta_generic_to_shared(s);
    if (tid == 0) {
        #pragma unroll
        for (int bbz = 0; bbz < 2; bbz++)
            #pragma unroll
            for (int i = 0; i < 3; i++) mbar_init(sbase + MBB(bbz, i));
        asm volatile("fence.mbarrier_init.release.cluster;" ::: "memory");
        #pragma unroll
        for (int bbz = 0; bbz < 2; bbz++) {
            mbar_expect(sbase + MBB(bbz, 1), 4128u);
            mbar_expect(sbase + MBB(bbz, 2), 2048u);
        }
    }
    __threadfence();     // g_wtp visible cluster-wide
    __syncthreads();
    csync();

    // ==================== MAIN LOOP (warp-split batches, 8 warps each) ====================
    const int bb = tid >> 8;           // warps 0-7 -> batch0, 8-15 -> batch1
    const int wg = tid & 255;
    const int cw = wg >> 5;            // chain warp 0..7
    const int S  = OFF_ST + bb * SBS;
    const int gb = b0 + bb;
    uint32_t rb[CS];
    #pragma unroll
    for (int r = 0; r < CS; r++) rb[r] = mapa_rank(sbase, r);
    const uint32_t mb_hp = sbase + MBB(bb, 0);
    const uint32_t mb_ac = sbase + MBB(bb, 1);
    const uint32_t mb_gi = sbase + MBB(bb, 2);
    const uint32_t MB_HP = MBB(bb, 0), MB_AC = MBB(bb, 1), MB_GI = MBB(bb, 2);

    float wtp_r = 0.f, p_r = 0.f;
    if (wg < 128) {
        wtp_r = g_wtp[(size_t)(gb * 128) * 128 + wg];
        p_r   = p_in[(size_t)(gb * 128) * 128 + wg];
    }

    for (int t = 0; t < 128; t++) {
        // ---- A: wait u-partials; u ----
        if (t) mbar_wait(mb_hp, (t - 1) & 1);
        if (wg == 0) mbar_expect(mb_hp, 4096u);
        if (wg < 128) {
            float u = wtp_r + s[OFF_WRB + wg];
            #pragma unroll
            for (int r = 0; r < CS; r++) u += s[S + P_UACB + r * 128 + wg];
            s[S + P_U + wg] = u;
            s[S + P_X + 128 + wg] = p_r;
        }
        barg(bb);

        // ---- B: scores (cw -> 4 q's; lanes take h-pairs via half2) ----
        {
            int q0 = cw * 4;
            const __half2* whs2 = (const __half2*)&s[OFF_WHS + bb * 2080];
            float a[4] = {0.f, 0.f, 0.f, 0.f};
            #pragma unroll
            for (int c = 0; c < 2; c++) {
                int h2 = c * 32 + lane;                     // 0..63
                float2 u2  = *(const float2*)&s[S + P_U + 2 * h2];
                float2 we2 = *(const float2*)&s[OFF_WE + 2 * h2];
                #pragma unroll
                for (int i = 0; i < 4; i++) {
                    float2 wf = __half22float2(whs2[(q0 + i) * 65 + h2]);
                    a[i] += fast_tanh(wf.x + u2.x) * we2.x
                          + fast_tanh(wf.y + u2.y) * we2.y;
                }
            }
            #pragma unroll
            for (int i = 0; i < 4; i++) a[i] = warp_sum(a[i]);
            if (lane == 0) {   // no-max softmax: |score| <= ||We||_1 ~ 5
                #pragma unroll
                for (int i = 0; i < 4; i++) s[S + P_PQ + q0 + i] = __expf(a[i]);
            }
        }
        barg(bb);

        // ---- push acc (v4-packed, rank-rotated) + l ----
        if (wg < 128) {
            const __half* whsh = (const __half*)&s[OFF_WHS + bb * 2080];
            float a = 0.f;
            #pragma unroll
            for (int q = 0; q < 32; q++)
                a += s[S + P_PQ + q] * __half2float(whsh[q * 130 + wg]);
            int lb = lane & ~3;
            float a0 = __shfl_sync(0xffffffffu, a, lb);
            float a1 = __shfl_sync(0xffffffffu, a, lb + 1);
            float a2 = __shfl_sync(0xffffffffu, a, lb + 2);
            float a3 = __shfl_sync(0xffffffffu, a, lb + 3);
            if ((lane & 3) == 0) {
                #pragma unroll
                for (int i = 0; i < CS; i++) {
                    int r = (rank + 1 + i) & 7;
                    st_async128(rb[r], S + P_ACB + rank * 128 + wg, MB_AC, a0, a1, a2, a3);
                }
            }
        } else if (cw == 4) {
            float l = warp_sum(s[S + P_PQ + lane]);
            if (lane == 0) {
                #pragma unroll
                for (int i = 0; i < CS; i++) {
                    int r = (rank + 1 + i) & 7;
                    st_async32(rb[r], S + P_LB + rank, MB_AC, l);
                }
            }
        }

        // ---- D_p: p-half of input gate (overlaps exch1 delivery) ----
        float dp[4];
        {
            int j0w = cw * 2;        // half2-word offset for j0 = cw*4
            #pragma unroll
            for (int i = 0; i < 4; i++) dp[i] = 0.f;
            const __half2* wgt2 = (const __half2*)&s[OFF_WGT];
            #pragma unroll
            for (int c = 4; c < 8; c++) {
                int k = c * 32 + lane;
                float xv = s[S + P_X + k];
                float2 w01 = __half22float2(wgt2[k * 17 + j0w]);
                float2 w23 = __half22float2(wgt2[k * 17 + j0w + 1]);
                dp[0] += w01.x * xv; dp[1] += w01.y * xv;
                dp[2] += w23.x * xv; dp[3] += w23.y * xv;
            }
        }

        // ---- C: wait acc; alpha ----
        mbar_wait(mb_ac, t & 1);
        if (wg == 0) mbar_expect(mb_ac, 4128u);
        if (wg < 128) {
            float a = 0.f, L = 0.f;
            #pragma unroll
            for (int r = 0; r < CS; r++) {
                a += s[S + P_ACB + r * 128 + wg];
                L += s[S + P_LB + r];
            }
            s[S + P_X + wg] = __fdividef(a, L);
        }
        barg(bb);

        // ---- D_alpha: alpha-half; finish gate ----
        {
            int j0 = cw * 4, j0w = cw * 2;
            float a[4] = {dp[0], dp[1], dp[2], dp[3]};
            const __half2* wgt2 = (const __half2*)&s[OFF_WGT];
            #pragma unroll
            for (int c = 0; c < 4; c++) {
                int k = c * 32 + lane;
                float xv = s[S + P_X + k];
                float2 w01 = __half22float2(wgt2[k * 17 + j0w]);
                float2 w23 = __half22float2(wgt2[k * 17 + j0w + 1]);
                a[0] += w01.x * xv; a[1] += w01.y * xv;
                a[2] += w23.x * xv; a[3] += w23.y * xv;
            }
            #pragma unroll
            for (int i = 0; i < 4; i++) a[i] = warp_sum(a[i]);
            if (lane == 0) {
                #pragma unroll
                for (int i = 0; i < 4; i++) {
                    float g = sigm(a[i] + s[OFF_WGB + j0 + i]);
                    s[S + P_XM + j0 + i] = g * s[S + P_X + rank * 32 + j0 + i];
                }
            }
        }
        barg(bb);

        // ---- Dfin: Wih k-partial gates (4 consecutive j per thread via LDS.64, v4 push) ----
        if (wg < 128) {
            int j = 4 * wg;                      // 0..508, 4-aligned: same owner block
            float a0 = 0.f, a1 = 0.f, a2 = 0.f, a3 = 0.f;
            #pragma unroll
            for (int k = 0; k < 32; k++) {
                float xm = s[S + P_XM + k];
                uint2 w = *(const uint2*)&s[OFF_WIHK + k * 258 + 2 * wg];
                float2 lo = __half22float2(*(const __half2*)&w.x);
                float2 hi = __half22float2(*(const __half2*)&w.y);
                a0 += lo.x * xm; a1 += lo.y * xm; a2 += hi.x * xm; a3 += hi.y * xm;
            }
            int hh = j & 127;
            int o = hh >> 4;
            int slot = (j >> 7) * 16 + (hh & 15);
            st_async128(rb[o], S + P_GIH + rank * 64 + slot, MB_GI, a0, a1, a2, a3);
        }

        // prefetch next step's wtp / p
        if (wg < 128) {
            int tn = (t < 127) ? t + 1 : 127;
            wtp_r = g_wtp[(size_t)(gb * 128 + tn) * 128 + wg];
            p_r   = p_in[(size_t)(gb * 128 + tn) * 128 + wg];
        }

        // ---- F: wait gih(t) [+ ghh(t)]; gate sums on one full warp; pointwise ----
        mbar_wait(mb_gi, t & 1);
        if (wg == 0) mbar_expect(mb_gi, 4096u);   // next phase: gih 2048 + ghh 2048
        if (wg < 32) {
            int jA = wg, jB = wg + 32;            // jA: i(0-15)/f(16-31); jB: g(32-47)/o(48-63)
            float vA = s[OFF_BIHH + jA], vB = s[OFF_BIHH + jB];
            #pragma unroll
            for (int r = 0; r < CS; r++) {
                vA += s[S + P_GIH + r * 64 + jA] + s[S + P_GHH + (t & 1) * 512 + r * 64 + jA];
                vB += s[S + P_GIH + r * 64 + jB] + s[S + P_GHH + (t & 1) * 512 + r * 64 + jB];
            }
            float fA = __shfl_sync(0xffffffffu, vA, (wg & 15) + 16);  // f(ss)
            float fB = __shfl_sync(0xffffffffu, vB, (wg & 15) + 16);  // o(ss)
            if (wg < 16) {
                float cn = sigm(fA) * s[S + P_C + wg] + sigm(vA) * tanh_ex(vB);
                float hn = sigm(fB) * tanh_ex(cn);
                s[S + P_C + wg]  = cn;
                s[S + P_HM + wg] = hn;
                out[(size_t)(gb * 128 + t) * 128 + rank * 16 + wg] = hn;
            }
        }
        barg(bb);

        // ---- push h-partials: u-parts (v4) -> mb_hp ; Whh gate-parts (v4) -> mb_gi(t+1) ----
        if (t < 127 && wg < 128) {
            {
                const __half* wrk = (const __half*)&s[OFF_WRK];
                float pu = 0.f;
                #pragma unroll
                for (int k = 0; k < 16; k++)
                    pu += __half2float(wrk[k * 132 + wg]) * s[S + P_HM + k];
                int lb = lane & ~3;
                float p0 = __shfl_sync(0xffffffffu, pu, lb);
                float p1 = __shfl_sync(0xffffffffu, pu, lb + 1);
                float p2 = __shfl_sync(0xffffffffu, pu, lb + 2);
                float p3 = __shfl_sync(0xffffffffu, pu, lb + 3);
                if ((lane & 3) == 0) {
                    #pragma unroll
                    for (int i = 0; i < CS; i++) {
                        int r = (rank + 1 + i) & 7;
                        st_async128(rb[r], S + P_UACB + rank * 128 + wg, MB_HP, p0, p1, p2, p3);
                    }
                }
            }
            {
                int j = 4 * wg;
                float a0 = 0.f, a1 = 0.f, a2 = 0.f, a3 = 0.f;
                #pragma unroll
                for (int k = 0; k < 16; k++) {
                    float hv = s[S + P_HM + k];
                    uint2 w = *(const uint2*)&s[OFF_WHHK + k * 258 + 2 * wg];
                    float2 lo = __half22float2(*(const __half2*)&w.x);
                    float2 hi = __half22float2(*(const __half2*)&w.y);
                    a0 += lo.x * hv; a1 += lo.y * hv; a2 += hi.x * hv; a3 += hi.y * hv;
                }
                int hh = j & 127;
                int o = hh >> 4;
                int slot = (j >> 7) * 16 + (hh & 15);
                st_async128(rb[o],
                            S + P_GHH + ((t + 1) & 1) * 512 + rank * 64 + slot, MB_GI,
                            a0, a1, a2, a3);
            }
        }
    }

    csync();   // no CTA exits while peers may still target its SMEM
}

extern "C" void kernel_launch(void* const* d_in, const int* in_sizes, int n_in,
                              void* d_out, int out_size) {
    (void)in_sizes; (void)n_in; (void)out_size;
    cudaFuncSetAttribute(mlstm_kernel, cudaFuncAttributeMaxDynamicSharedMemorySize,
                         SMEM_FLOATS * (int)sizeof(float));
    mlstm_kernel<<<64, TPB, SMEM_FLOATS * sizeof(float)>>>(
        (const float*)d_in[0],  (const float*)d_in[1],
        (const float*)d_in[2],  (const float*)d_in[3],
        (const float*)d_in[4],  (const float*)d_in[5],
        (const float*)d_in[6],  (const float*)d_in[7],
        (const float*)d_in[8],
        (const float*)d_in[10], (const float*)d_in[11],
        (const float*)d_in[12], (const float*)d_in[13],
        (const float*)d_in[14], (const float*)d_in[15],
        (float*)d_out);
}

// round 17
// speedup vs baseline: 1.8360x; 1.8360x over previous
#include <cuda_runtime.h>
#include <cuda_fp16.h>
#include <cooperative_groups.h>

namespace cg = cooperative_groups;

#define CS   8
#define TPB  512

// ---- shared memory layout (float/u32-word offsets) ----
// fp16 weight arrays (stored as half in word-addressed regions)
static constexpr int OFF_WHS  = 0;       // 2 * 32*65 words : Whs[bb][q][h2] (half2 per word)
static constexpr int OFF_WGT  = 4160;    // 256*17 words    : WgT[k][j2]
static constexpr int OFF_WIHK = 8512;    // 32*258 words    : WihT_k[k][j2]
static constexpr int OFF_WHHK = 16768;   // 16*258 words    : WhhT_k[k][j2]
static constexpr int OFF_WRK  = 20896;   // 16*66 words     : WrT_k[k][j] (half idx k*132+j)
static constexpr int OFF_WE   = 21952;   // 128 fp32
static constexpr int OFF_WRB  = 22080;   // 128 fp32
static constexpr int OFF_WGB  = 22208;   // 32 fp32
static constexpr int OFF_BIHH = 22240;   // 64 fp32
static constexpr int OFF_MBAR = 22304;   // 16 floats = 8 u64 slots (6 used)
static constexpr int OFF_ST   = 22320;   // per-batch state below
// per-batch state, stride SBS (all fp32, identical to R12)
static constexpr int P_U    = 0;      // 128
static constexpr int P_X    = 128;    // 256 : [alpha, p_t]
static constexpr int P_PQ   = 384;    // 32
static constexpr int P_XM   = 416;    // 32
static constexpr int P_HM   = 448;    // 16
static constexpr int P_C    = 464;    // 16
static constexpr int P_ACB  = 480;    // 8*128 (pushed)
static constexpr int P_LB   = 1504;   // 8     (pushed)
static constexpr int P_UACB = 1512;   // 8*128 (pushed)
static constexpr int P_GIH  = 2536;   // 8*64  (pushed)
static constexpr int P_GHH  = 3048;   // 2*8*64 parity buffered (pushed)
static constexpr int SBS    = 4072;
static constexpr int OFF_STG = OFF_ST + 2 * SBS;     // 30464 : prologue staging (25088)
static constexpr int SMEM_FLOATS = OFF_STG + 25088;  // 55552 floats = 222208 B

__device__ __forceinline__ uint32_t MBB(int bb, int i) {   // i: 0 hp(u), 1 acc, 2 gih+ghh
    return (uint32_t)(OFF_MBAR * 4 + (bb * 3 + i) * 8);
}

__device__ float g_wtp[16 * 128 * 128];   // wt_pre scratch [B][P][H]

__device__ __forceinline__ float fast_tanh(float x) {
    float y; asm("tanh.approx.f32 %0, %1;" : "=f"(y) : "f"(x)); return y;
}
__device__ __forceinline__ float sigm(float x) {
    return __fdividef(1.f, 1.f + __expf(-x));
}
__device__ __forceinline__ float tanh_ex(float x) {
    float e = __expf(2.f * x);
    return 1.f - __fdividef(2.f, e + 1.f);
}
__device__ __forceinline__ float warp_sum(float v) {
    #pragma unroll
    for (int o = 16; o; o >>= 1) v += __shfl_xor_sync(0xffffffffu, v, o);
    return v;
}
__device__ __forceinline__ uint32_t mapa_rank(uint32_t base, int r) {
    uint32_t rm;
    asm("mapa.shared::cluster.u32 %0, %1, %2;" : "=r"(rm) : "r"(base), "r"(r));
    return rm;
}
__device__ __forceinline__ void st_async32(uint32_t rbase, int foff, uint32_t mb_byte, float v) {
    asm volatile("st.async.shared::cluster.mbarrier::complete_tx::bytes.b32 [%0], %1, [%2];"
                 :: "r"(rbase + (uint32_t)foff * 4u), "r"(__float_as_uint(v)),
                    "r"(rbase + mb_byte) : "memory");
}
__device__ __forceinline__ void st_async128(uint32_t rbase, int foff, uint32_t mb_byte,
                                            float a, float b, float c, float d) {
    asm volatile("st.async.shared::cluster.mbarrier::complete_tx::bytes.v4.b32 [%0], {%1,%2,%3,%4}, [%5];"
                 :: "r"(rbase + (uint32_t)foff * 4u),
                    "r"(__float_as_uint(a)), "r"(__float_as_uint(b)),
                    "r"(__float_as_uint(c)), "r"(__float_as_uint(d)),
                    "r"(rbase + mb_byte) : "memory");
}
__device__ __forceinline__ void mbar_init(uint32_t addr) {
    asm volatile("mbarrier.init.shared.b64 [%0], 1;" :: "r"(addr) : "memory");
}
__device__ __forceinline__ void mbar_expect(uint32_t addr, uint32_t bytes) {
    asm volatile("mbarrier.arrive.expect_tx.shared.b64 _, [%0], %1;" :: "r"(addr), "r"(bytes) : "memory");
}
__device__ __forceinline__ void mbar_wait(uint32_t addr, uint32_t parity) {
    asm volatile(
        "{\n\t.reg .pred P1;\n\t"
        "WL%=:\n\t"
        "mbarrier.try_wait.parity.acquire.cluster.shared::cta.b64 P1, [%0], %1, 0x989680;\n\t"
        "@P1 bra.uni WD%=;\n\t"
        "bra.uni WL%=;\n\t"
        "WD%=:\n\t}"
        :: "r"(addr), "r"(parity) : "memory");
}
__device__ __forceinline__ void barg(int bb) {
    asm volatile("bar.sync %0, 256;" :: "r"(1 + bb) : "memory");
}
__device__ __forceinline__ void csync() {
    asm volatile("barrier.cluster.arrive.aligned;" ::: "memory");
    asm volatile("barrier.cluster.wait.aligned;" ::: "memory");
}

__global__ void __launch_bounds__(TPB, 1) __cluster_dims__(CS, 1, 1)
mlstm_kernel(const float* __restrict__ p_in,  const float* __restrict__ q_in,
             const float* __restrict__ Ws_w,  const float* __restrict__ Ws_b,
             const float* __restrict__ Wt_w,  const float* __restrict__ Wt_b,
             const float* __restrict__ Wr_w,  const float* __restrict__ Wr_b,
             const float* __restrict__ We_w,
             const float* __restrict__ Wg_w,  const float* __restrict__ Wg_b,
             const float* __restrict__ Wih,   const float* __restrict__ Whh,
             const float* __restrict__ bih,   const float* __restrict__ bhh,
             float* __restrict__ out)
{
    extern __shared__ float s[];
    __half* sh = (__half*)s;
    cg::cluster_group cl = cg::this_cluster();
    const int rank = (int)cl.block_rank();
    const int b0   = (int)(blockIdx.x >> 3) * 2;
    const int tid  = (int)threadIdx.x;
    const int lane = tid & 31;

    // ============================ PROLOGUE ============================
    // P1: Whs[bb] = q(32 rows) @ Ws^T + b  (Ws staged pad132 at OFF_STG, q at OFF_STG+16896)
    for (int i4 = tid; i4 < 4096; i4 += TPB) {
        int hh = i4 >> 5, k = i4 & 31;
        *(float4*)&s[OFF_STG + hh * 132 + k * 4] = ((const float4*)Ws_w)[i4];
    }
    #pragma unroll
    for (int bb = 0; bb < 2; bb++)
        for (int i4 = tid; i4 < 1024; i4 += TPB)
            ((float4*)&s[OFF_STG + 16896 + bb * 4096])[i4] =
                ((const float4*)(q_in + (size_t)((b0 + bb) * 256 + rank * 32) * 128))[i4];
    __syncthreads();
    #pragma unroll
    for (int bb = 0; bb < 2; bb++) {
        int hh = tid & 127, q0 = (tid >> 7) * 8;
        const float4* wrow = (const float4*)&s[OFF_STG + hh * 132];
        float acc[8];
        float sb = Ws_b[hh];
        #pragma unroll
        for (int i = 0; i < 8; i++) acc[i] = sb;
        for (int k = 0; k < 32; k++) {
            float4 w = wrow[k];
            #pragma unroll
            for (int i = 0; i < 8; i++) {
                float4 qv = *(const float4*)&s[OFF_STG + 16896 + bb * 4096 + (q0 + i) * 128 + k * 4];
                acc[i] += w.x * qv.x + w.y * qv.y + w.z * qv.z + w.w * qv.w;
            }
        }
        #pragma unroll
        for (int i = 0; i < 8; i++)
            sh[(OFF_WHS + bb * 2080) * 2 + (q0 + i) * 130 + hh] = __float2half(acc[i]);
    }
    __syncthreads();

    // P2: wt_pre[bb] = p(16 rows) @ Wt^T + b -> gmem scratch
    for (int i4 = tid; i4 < 4096; i4 += TPB) {
        int hh = i4 >> 5, k = i4 & 31;
        *(float4*)&s[OFF_STG + hh * 132 + k * 4] = ((const float4*)Wt_w)[i4];
    }
    #pragma unroll
    for (int bb = 0; bb < 2; bb++)
        for (int i4 = tid; i4 < 512; i4 += TPB)
            ((float4*)&s[OFF_STG + 16896 + bb * 2048])[i4] =
                ((const float4*)(p_in + (size_t)((b0 + bb) * 128 + rank * 16) * 128))[i4];
    __syncthreads();
    #pragma unroll
    for (int bb = 0; bb < 2; bb++) {
        int hh = tid & 127, t0 = (tid >> 7) * 4;
        const float4* wrow = (const float4*)&s[OFF_STG + hh * 132];
        float acc[4];
        float bt = Wt_b[hh];
        #pragma unroll
        for (int i = 0; i < 4; i++) acc[i] = bt;
        for (int k = 0; k < 32; k++) {
            float4 w = wrow[k];
            #pragma unroll
            for (int i = 0; i < 4; i++) {
                float4 pv = *(const float4*)&s[OFF_STG + 16896 + bb * 2048 + (t0 + i) * 128 + k * 4];
                acc[i] += w.x * pv.x + w.y * pv.y + w.z * pv.z + w.w * pv.w;
            }
        }
        #pragma unroll
        for (int i = 0; i < 4; i++)
            g_wtp[(size_t)((b0 + bb) * 128 + rank * 16 + t0 + i) * 128 + hh] = acc[i];
    }
    __syncthreads();

    // P3: resident weights (k-partitioned, fp16)
    for (int idx = tid; idx < 512 * 32; idx += TPB) {       // WihT_k [k][516 halves]
        int j = idx >> 5, kk = idx & 31;
        sh[OFF_WIHK * 2 + kk * 516 + j] = __float2half(Wih[(size_t)j * 256 + rank * 32 + kk]);
    }
    for (int idx = tid; idx < 512 * 16; idx += TPB) {       // WhhT_k [k][516 halves]
        int j = idx >> 4, kk = idx & 15;
        sh[OFF_WHHK * 2 + kk * 516 + j] = __float2half(Whh[(size_t)j * 128 + rank * 16 + kk]);
    }
    for (int idx = tid; idx < 128 * 16; idx += TPB) {       // WrT_k [k][132 halves]
        int j = idx >> 4, kk = idx & 15;
        sh[OFF_WRK * 2 + kk * 132 + j] = __float2half(Wr_w[(size_t)j * 128 + rank * 16 + kk]);
    }
    for (int idx = tid; idx < 8192; idx += TPB) {           // WgT [k][34 halves]
        int j = idx >> 8, k = idx & 255;
        sh[OFF_WGT * 2 + k * 34 + j] = __float2half(Wg_w[(size_t)(rank * 32 + j) * 256 + k]);
    }
    if (tid < 128) { s[OFF_WE + tid] = We_w[tid]; s[OFF_WRB + tid] = Wr_b[tid]; }
    if (tid < 32) s[OFF_WGB + tid] = Wg_b[rank * 32 + tid];
    if (tid < 64) {
        int grow = (tid >> 4) * 128 + rank * 16 + (tid & 15);
        s[OFF_BIHH + tid] = bih[grow] + bhh[grow];
    }
    #pragma unroll
    for (int bbz = 0; bbz < 2; bbz++) {
        int S = OFF_ST + bbz * SBS;
        for (int i = tid; i < 1024; i += TPB) { s[S + P_UACB + i] = 0.f; s[S + P_GHH + i] = 0.f; }
        if (tid < 16) s[S + P_C + tid] = 0.f;
    }
    const uint32_t sbase = (uint32_t)__cvta_generic_to_shared(s);
    if (tid == 0) {
        #pragma unroll
        for (int bbz = 0; bbz < 2; bbz++)
            #pragma unroll
            for (int i = 0; i < 3; i++) mbar_init(sbase + MBB(bbz, i));
        asm volatile("fence.mbarrier_init.release.cluster;" ::: "memory");
        // phase-0 expects: acc 4096+32; gih 2048 (no ghh arrives for step 0)
        #pragma unroll
        for (int bbz = 0; bbz < 2; bbz++) {
            mbar_expect(sbase + MBB(bbz, 1), 4128u);
            mbar_expect(sbase + MBB(bbz, 2), 2048u);
        }
    }
    __threadfence();     // g_wtp visible cluster-wide
    __syncthreads();
    csync();

    // ==================== MAIN LOOP (warp-split batches, 8 warps each) ====================
    const int bb = tid >> 8;           // warps 0-7 -> batch0, 8-15 -> batch1
    const int wg = tid & 255;
    const int cw = wg >> 5;            // chain warp 0..7
    const int S  = OFF_ST + bb * SBS;
    const int gb = b0 + bb;
    uint32_t rb[CS];
    #pragma unroll
    for (int r = 0; r < CS; r++) rb[r] = mapa_rank(sbase, r);
    const uint32_t mb_hp = sbase + MBB(bb, 0);
    const uint32_t mb_ac = sbase + MBB(bb, 1);
    const uint32_t mb_gi = sbase + MBB(bb, 2);
    const uint32_t MB_HP = MBB(bb, 0), MB_AC = MBB(bb, 1), MB_GI = MBB(bb, 2);

    float wtp_r = 0.f, p_r = 0.f;
    if (wg < 128) {
        wtp_r = g_wtp[(size_t)(gb * 128) * 128 + wg];
        p_r   = p_in[(size_t)(gb * 128) * 128 + wg];
    }

    for (int t = 0; t < 128; t++) {
        // ---- A: wait u-partials; u ----
        if (t) mbar_wait(mb_hp, (t - 1) & 1);
        if (wg == 0) mbar_expect(mb_hp, 4096u);
        if (wg < 128) {
            float u = wtp_r + s[OFF_WRB + wg];
            #pragma unroll
            for (int r = 0; r < CS; r++) u += s[S + P_UACB + r * 128 + wg];
            s[S + P_U + wg] = u;
            s[S + P_X + 128 + wg] = p_r;
        }
        barg(bb);

        // ---- B: scores (cw -> 4 q's; lanes take h-pairs via half2) ----
        {
            int q0 = cw * 4;
            const __half2* whs2 = (const __half2*)&s[OFF_WHS + bb * 2080];
            float a[4] = {0.f, 0.f, 0.f, 0.f};
            #pragma unroll
            for (int c = 0; c < 2; c++) {
                int h2 = c * 32 + lane;                     // 0..63
                float2 u2  = *(const float2*)&s[S + P_U + 2 * h2];
                float2 we2 = *(const float2*)&s[OFF_WE + 2 * h2];
                #pragma unroll
                for (int i = 0; i < 4; i++) {
                    float2 wf = __half22float2(whs2[(q0 + i) * 65 + h2]);
                    a[i] += fast_tanh(wf.x + u2.x) * we2.x
                          + fast_tanh(wf.y + u2.y) * we2.y;
                }
            }
            #pragma unroll
            for (int i = 0; i < 4; i++) a[i] = warp_sum(a[i]);
            if (lane == 0) {   // no-max softmax: |score| <= ||We||_1 ~ 5
                #pragma unroll
                for (int i = 0; i < 4; i++) s[S + P_PQ + q0 + i] = __expf(a[i]);
            }
        }
        barg(bb);

        // ---- push acc (v4-packed, rank-rotated) + l ----
        if (wg < 128) {
            const __half* whsh = (const __half*)&s[OFF_WHS + bb * 2080];
            float a = 0.f;
            #pragma unroll
            for (int q = 0; q < 32; q++)
                a += s[S + P_PQ + q] * __half2float(whsh[q * 130 + wg]);
            int lb = lane & ~3;
            float a0 = __shfl_sync(0xffffffffu, a, lb);
            float a1 = __shfl_sync(0xffffffffu, a, lb + 1);
            float a2 = __shfl_sync(0xffffffffu, a, lb + 2);
            float a3 = __shfl_sync(0xffffffffu, a, lb + 3);
            if ((lane & 3) == 0) {
                #pragma unroll
                for (int i = 0; i < CS; i++) {
                    int r = (rank + 1 + i) & 7;
                    st_async128(rb[r], S + P_ACB + rank * 128 + wg, MB_AC, a0, a1, a2, a3);
                }
            }
        } else if (cw == 4) {
            float l = warp_sum(s[S + P_PQ + lane]);
            if (lane == 0) {
                #pragma unroll
                for (int i = 0; i < CS; i++) {
                    int r = (rank + 1 + i) & 7;
                    st_async32(rb[r], S + P_LB + rank, MB_AC, l);
                }
            }
        }

        // ---- D_p: p-half of input gate (overlaps exch1 delivery) ----
        float dp[4];
        {
            int j0w = cw * 2;        // half2-word offset for j0 = cw*4
            #pragma unroll
            for (int i = 0; i < 4; i++) dp[i] = 0.f;
            const __half2* wgt2 = (const __half2*)&s[OFF_WGT];
            #pragma unroll
            for (int c = 4; c < 8; c++) {
                int k = c * 32 + lane;
                float xv = s[S + P_X + k];
                float2 w01 = __half22float2(wgt2[k * 17 + j0w]);
                float2 w23 = __half22float2(wgt2[k * 17 + j0w + 1]);
                dp[0] += w01.x * xv; dp[1] += w01.y * xv;
                dp[2] += w23.x * xv; dp[3] += w23.y * xv;
            }
        }

        // ---- C: wait acc; alpha ----
        mbar_wait(mb_ac, t & 1);
        if (wg == 0) mbar_expect(mb_ac, 4128u);
        if (wg < 128) {
            float a = 0.f, L = 0.f;
            #pragma unroll
            for (int r = 0; r < CS; r++) {
                a += s[S + P_ACB + r * 128 + wg];
                L += s[S + P_LB + r];
            }
            s[S + P_X + wg] = __fdividef(a, L);
        }
        barg(bb);

        // ---- D_alpha: alpha-half; finish gate ----
        {
            int j0 = cw * 4, j0w = cw * 2;
            float a[4] = {dp[0], dp[1], dp[2], dp[3]};
            const __half2* wgt2 = (const __half2*)&s[OFF_WGT];
            #pragma unroll
            for (int c = 0; c < 4; c++) {
                int k = c * 32 + lane;
                float xv = s[S + P_X + k];
                float2 w01 = __half22float2(wgt2[k * 17 + j0w]);
                float2 w23 = __half22float2(wgt2[k * 17 + j0w + 1]);
                a[0] += w01.x * xv; a[1] += w01.y * xv;
                a[2] += w23.x * xv; a[3] += w23.y * xv;
            }
            #pragma unroll
            for (int i = 0; i < 4; i++) a[i] = warp_sum(a[i]);
            if (lane == 0) {
                #pragma unroll
                for (int i = 0; i < 4; i++) {
                    float g = sigm(a[i] + s[OFF_WGB + j0 + i]);
                    s[S + P_XM + j0 + i] = g * s[S + P_X + rank * 32 + j0 + i];
                }
            }
        }
        barg(bb);

        // ---- Dfin: Wih k-partial gates (4 consecutive j per thread via LDS.64, v4 push) ----
        if (wg < 128) {
            int j = 4 * wg;                      // 0..508, 4-aligned: same owner block
            float a0 = 0.f, a1 = 0.f, a2 = 0.f, a3 = 0.f;
            #pragma unroll
            for (int k = 0; k < 32; k++) {
                float xm = s[S + P_XM + k];
                uint2 w = *(const uint2*)&s[OFF_WIHK + k * 258 + 2 * wg];
                float2 lo = __half22float2(*(const __half2*)&w.x);
                float2 hi = __half22float2(*(const __half2*)&w.y);
                a0 += lo.x * xm; a1 += lo.y * xm; a2 += hi.x * xm; a3 += hi.y * xm;
            }
            int hh = j & 127;
            int o = hh >> 4;
            int slot = (j >> 7) * 16 + (hh & 15);
            st_async128(rb[o], S + P_GIH + rank * 64 + slot, MB_GI, a0, a1, a2, a3);
        }

        // prefetch next step's wtp / p
        if (wg < 128) {
            int tn = (t < 127) ? t + 1 : 127;
            wtp_r = g_wtp[(size_t)(gb * 128 + tn) * 128 + wg];
            p_r   = p_in[(size_t)(gb * 128 + tn) * 128 + wg];
        }

        // ---- F: wait gih(t) [+ ghh(t), pushed at end of t-1]; pointwise ----
        mbar_wait(mb_gi, t & 1);
        if (wg == 0) mbar_expect(mb_gi, 4096u);   // next phase: gih 2048 + ghh 2048
        if (wg < 16) {
            float g[4];
            #pragma unroll
            for (int gt = 0; gt < 4; gt++) {
                float v = s[OFF_BIHH + gt * 16 + wg];
                #pragma unroll
                for (int r = 0; r < CS; r++) {
                    v += s[S + P_GIH + r * 64 + gt * 16 + wg];
                    v += s[S + P_GHH + (t & 1) * 512 + r * 64 + gt * 16 + wg];
                }
                g[gt] = v;
            }
            float cn = sigm(g[1]) * s[S + P_C + wg] + sigm(g[0]) * tanh_ex(g[2]);
            float hn = sigm(g[3]) * tanh_ex(cn);
            s[S + P_C + wg]  = cn;
            s[S + P_HM + wg] = hn;
            out[(size_t)(gb * 128 + t) * 128 + rank * 16 + wg] = hn;
        }
        barg(bb);

        // ---- push h-partials: u-parts (v4) -> mb_hp ; Whh gate-parts (v4) -> mb_gi(t+1) ----
        if (t < 127 && wg < 128) {
            {
                const __half* wrk = (const __half*)&s[OFF_WRK];
                float pu = 0.f;
                #pragma unroll
                for (int k = 0; k < 16; k++)
                    pu += __half2float(wrk[k * 132 + wg]) * s[S + P_HM + k];
                int lb = lane & ~3;
                float p0 = __shfl_sync(0xffffffffu, pu, lb);
                float p1 = __shfl_sync(0xffffffffu, pu, lb + 1);
                float p2 = __shfl_sync(0xffffffffu, pu, lb + 2);
                float p3 = __shfl_sync(0xffffffffu, pu, lb + 3);
                if ((lane & 3) == 0) {
                    #pragma unroll
                    for (int i = 0; i < CS; i++) {
                        int r = (rank + 1 + i) & 7;
                        st_async128(rb[r], S + P_UACB + rank * 128 + wg, MB_HP, p0, p1, p2, p3);
                    }
                }
            }
            {
                int j = 4 * wg;
                float a0 = 0.f, a1 = 0.f, a2 = 0.f, a3 = 0.f;
                #pragma unroll
                for (int k = 0; k < 16; k++) {
                    float hv = s[S + P_HM + k];
                    uint2 w = *(const uint2*)&s[OFF_WHHK + k * 258 + 2 * wg];
                    float2 lo = __half22float2(*(const __half2*)&w.x);
                    float2 hi = __half22float2(*(const __half2*)&w.y);
                    a0 += lo.x * hv; a1 += lo.y * hv; a2 += hi.x * hv; a3 += hi.y * hv;
                }
                int hh = j & 127;
                int o = hh >> 4;
                int slot = (j >> 7) * 16 + (hh & 15);
                st_async128(rb[o],
                            S + P_GHH + ((t + 1) & 1) * 512 + rank * 64 + slot, MB_GI,
                            a0, a1, a2, a3);
            }
        }
    }

    csync();   // no CTA exits while peers may still target its SMEM
}

extern "C" void kernel_launch(void* const* d_in, const int* in_sizes, int n_in,
                              void* d_out, int out_size) {
    (void)in_sizes; (void)n_in; (void)out_size;
    cudaFuncSetAttribute(mlstm_kernel, cudaFuncAttributeMaxDynamicSharedMemorySize,
                         SMEM_FLOATS * (int)sizeof(float));
    mlstm_kernel<<<64, TPB, SMEM_FLOATS * sizeof(float)>>>(
        (const float*)d_in[0],  (const float*)d_in[1],
        (const float*)d_in[2],  (const float*)d_in[3],
        (const float*)d_in[4],  (const float*)d_in[5],
        (const float*)d_in[6],  (const float*)d_in[7],
        (const float*)d_in[8],
        (const float*)d_in[10], (const float*)d_in[11],
        (const float*)d_in[12], (const float*)d_in[13],
        (const float*)d_in[14], (const float*)d_in[15],
        (float*)d_out);
}